// round 9
// baseline (speedup 1.0000x reference)
#include <cuda_runtime.h>
#include <cstdint>

#define NROWS 1024
#define MROWS 1024
#define DIM   512

__device__ float g_hx[NROWS * DIM];
__device__ float g_hy[MROWS * DIM];
__device__ float g_Wt[2 * DIM * DIM];   // Wt[z][n][k] = W1[z*DIM + k][n]

typedef unsigned long long u64;

#define ADD2(d, a, b) \
    asm("add.rn.f32x2 %0, %1, %2;" : "=l"(d) : "l"(a), "l"(b))
#define FMA2(d, a, b, c) \
    asm("fma.rn.f32x2 %0, %1, %2, %3;" : "=l"(d) : "l"(a), "l"(b), "l"(c))

__device__ __forceinline__ u64 relu2(u64 s) {
    unsigned int lo, hi;
    asm("mov.b64 {%0,%1}, %2;" : "=r"(lo), "=r"(hi) : "l"(s));
    float f0 = fmaxf(__uint_as_float(lo), 0.0f);
    float f1 = fmaxf(__uint_as_float(hi), 0.0f);
    u64 r;
    asm("mov.b64 %0, {%1,%2};"
        : "=l"(r) : "r"(__float_as_uint(f0)), "r"(__float_as_uint(f1)));
    return r;
}

__device__ __forceinline__ float hsum2(u64 s) {
    unsigned int lo, hi;
    asm("mov.b64 {%0,%1}, %2;" : "=r"(lo), "=r"(hi) : "l"(s));
    return __uint_as_float(lo) + __uint_as_float(hi);
}

__device__ __forceinline__ void cpa16(uint32_t s, const void* g) {
    asm volatile("cp.async.cg.shared.global [%0], [%1], 16;" :: "r"(s), "l"(g));
}
__device__ __forceinline__ void cpa8(uint32_t s, const void* g) {
    asm volatile("cp.async.ca.shared.global [%0], [%1], 8;" :: "r"(s), "l"(g));
}
#define CP_COMMIT() asm volatile("cp.async.commit_group;" ::: "memory")
#define CP_WAIT(n)  asm volatile("cp.async.wait_group %0;" :: "n"(n) : "memory")

// -------------------------------------------------------------------------
// W transpose: g_Wt[z][n][k] = W1[z*DIM + k][n]
// -------------------------------------------------------------------------
__global__ void __launch_bounds__(256) transpose_w(const float* __restrict__ W1) {
    __shared__ float t[32][33];
    const int z  = blockIdx.z;
    const int k0 = blockIdx.x * 32;
    const int n0 = blockIdx.y * 32;
    const int c  = threadIdx.x & 31;
    const int r0 = threadIdx.x >> 5;   // 0..7
#pragma unroll
    for (int rr = 0; rr < 4; rr++) {
        int r = r0 + rr * 8;
        t[r][c] = W1[(z * DIM + k0 + r) * DIM + n0 + c];
    }
    __syncthreads();
#pragma unroll
    for (int rr = 0; rr < 4; rr++) {
        int r = r0 + rr * 8;
        g_Wt[z * DIM * DIM + (n0 + r) * DIM + k0 + c] = t[c][r];
    }
}

// -------------------------------------------------------------------------
// GEMM: C[m][n] = sum_k A[m][k]*Wt[n][k], cp.async double-buffered.
// As stride 36 (16B cp.async, broadcast consumer), Bs stride 34 (8B
// cp.async, conflict-free LDS.64 consumer). 64x64 tile, 4x4/thread.
// -------------------------------------------------------------------------
__global__ void __launch_bounds__(256, 3) gemm_dual(const float* __restrict__ x,
                                                    const float* __restrict__ y) {
    const int z = blockIdx.z;
    const float* __restrict__ A  = (z == 0) ? x : y;
    const float* __restrict__ Wt = g_Wt + z * DIM * DIM;
    float* __restrict__ C = (z == 0) ? g_hx : g_hy;

    __shared__ float As[2][64][36];
    __shared__ float Bs[2][64][34];

    const int tid = threadIdx.x;
    const int tn = tid & 15;
    const int tm = tid >> 4;
    const int m0 = blockIdx.y * 64;
    const int n0 = blockIdx.x * 64;

    // A loader: 64 rows x 8 16B-chunks
    const int ar = tid >> 3;       // row 0..31, +32
    const int ac = tid & 7;        // chunk
    // B loader: 64 rows x 16 8B-chunks
    const int br = tid >> 4;       // row 0..15, +16,+32,+48
    const int bc = tid & 15;       // chunk

    uint32_t sAs[2], sBs[2];
    sAs[0] = (uint32_t)__cvta_generic_to_shared(&As[0][0][0]);
    sAs[1] = (uint32_t)__cvta_generic_to_shared(&As[1][0][0]);
    sBs[0] = (uint32_t)__cvta_generic_to_shared(&Bs[0][0][0]);
    sBs[1] = (uint32_t)__cvta_generic_to_shared(&Bs[1][0][0]);

    u64 acc[4][4];
#pragma unroll
    for (int i = 0; i < 4; i++)
#pragma unroll
        for (int j = 0; j < 4; j++) acc[i][j] = 0ULL;

    // issue tile loads for k-chunk k0 into buffer bf
    auto issue = [&](int bf, int k0) {
#pragma unroll
        for (int it = 0; it < 2; it++)
            cpa16(sAs[bf] + ((ar + it * 32) * 36 + ac * 4) * 4,
                  &A[(m0 + ar + it * 32) * DIM + k0 + ac * 4]);
#pragma unroll
        for (int it = 0; it < 4; it++)
            cpa8(sBs[bf] + ((br + it * 16) * 34 + bc * 2) * 4,
                 &Wt[(n0 + br + it * 16) * DIM + k0 + bc * 2]);
    };

    issue(0, 0);
    CP_COMMIT();

    for (int k0i = 0; k0i < 16; k0i++) {
        const int buf = k0i & 1;
        if (k0i < 15) {
            issue(buf ^ 1, (k0i + 1) * 32);
            CP_COMMIT();
            CP_WAIT(1);
        } else {
            CP_WAIT(0);
        }
        __syncthreads();

#pragma unroll
        for (int kk = 0; kk < 32; kk += 2) {
            u64 a2[4], b2[4];
#pragma unroll
            for (int i = 0; i < 4; i++)
                a2[i] = *(const u64*)&As[buf][tm * 4 + i][kk];
#pragma unroll
            for (int j = 0; j < 4; j++)
                b2[j] = *(const u64*)&Bs[buf][tn + 16 * j][kk];
#pragma unroll
            for (int i = 0; i < 4; i++)
#pragma unroll
                for (int j = 0; j < 4; j++)
                    FMA2(acc[i][j], a2[i], b2[j], acc[i][j]);
        }
        __syncthreads();
    }

#pragma unroll
    for (int i = 0; i < 4; i++)
#pragma unroll
        for (int j = 0; j < 4; j++)
            C[(m0 + tm * 4 + i) * DIM + n0 + tn + 16 * j] = hsum2(acc[i][j]);
}

// -------------------------------------------------------------------------
// Pairwise: out[i][j] = sum_d relu(hx[i][d]+hy[j][d]) * w2[d].
// cp.async double-buffered 32-d chunks, stride-36 rows (16B-aligned,
// conflict-free strided LDS.128), 64x64 tile, 4x4/thread, 3 blocks/SM.
// -------------------------------------------------------------------------
__global__ void __launch_bounds__(256, 3) pairwise_kernel(const float* __restrict__ w2,
                                                          float* __restrict__ out) {
    __shared__ float xs[2][64][36];
    __shared__ float ys[2][64][36];
    __shared__ float w2s[DIM];

    const int tid = threadIdx.x;
    const int tx = tid & 15;
    const int ty = tid >> 4;
    const int i0 = blockIdx.y * 64;
    const int j0 = blockIdx.x * 64;

    const int lr = tid >> 3;   // row 0..31, +32
    const int lc = tid & 7;    // 16B chunk

    uint32_t sxs[2], sys[2];
    sxs[0] = (uint32_t)__cvta_generic_to_shared(&xs[0][0][0]);
    sxs[1] = (uint32_t)__cvta_generic_to_shared(&xs[1][0][0]);
    sys[0] = (uint32_t)__cvta_generic_to_shared(&ys[0][0][0]);
    sys[1] = (uint32_t)__cvta_generic_to_shared(&ys[1][0][0]);

    u64 acc[4][4];
#pragma unroll
    for (int i = 0; i < 4; i++)
#pragma unroll
        for (int j = 0; j < 4; j++) acc[i][j] = 0ULL;

    if (tid < 128)
        *(float4*)&w2s[tid * 4] = *(const float4*)&w2[tid * 4];

    auto issue = [&](int bf, int dg) {
#pragma unroll
        for (int it = 0; it < 2; it++) {
            cpa16(sxs[bf] + ((lr + it * 32) * 36 + lc * 4) * 4,
                  &g_hx[(i0 + lr + it * 32) * DIM + dg + lc * 4]);
            cpa16(sys[bf] + ((lr + it * 32) * 36 + lc * 4) * 4,
                  &g_hy[(j0 + lr + it * 32) * DIM + dg + lc * 4]);
        }
    };

    issue(0, 0);
    CP_COMMIT();

    for (int ch = 0; ch < 16; ch++) {
        const int buf = ch & 1;
        if (ch < 15) {
            issue(buf ^ 1, (ch + 1) * 32);
            CP_COMMIT();
            CP_WAIT(1);
        } else {
            CP_WAIT(0);
        }
        __syncthreads();

        const float* __restrict__ w2p = &w2s[ch * 32];
#pragma unroll
        for (int dd = 0; dd < 32; dd += 4) {
            u64 a[4][2], b[4][2];
#pragma unroll
            for (int ti = 0; ti < 4; ti++) {
                ulonglong2 av = *(const ulonglong2*)&xs[buf][ty + 16 * ti][dd];
                a[ti][0] = av.x;
                a[ti][1] = av.y;
            }
#pragma unroll
            for (int tj = 0; tj < 4; tj++) {
                ulonglong2 bv = *(const ulonglong2*)&ys[buf][tx + 16 * tj][dd];
                b[tj][0] = bv.x;
                b[tj][1] = bv.y;
            }
            ulonglong2 wv = *(const ulonglong2*)&w2p[dd];
            u64 w[2];
            w[0] = wv.x;
            w[1] = wv.y;
#pragma unroll
            for (int ti = 0; ti < 4; ti++)
#pragma unroll
                for (int tj = 0; tj < 4; tj++) {
#pragma unroll
                    for (int p = 0; p < 2; p++) {
                        u64 s;
                        ADD2(s, a[ti][p], b[tj][p]);
                        s = relu2(s);
                        FMA2(acc[ti][tj], s, w[p], acc[ti][tj]);
                    }
                }
        }
        __syncthreads();
    }

#pragma unroll
    for (int ti = 0; ti < 4; ti++)
#pragma unroll
        for (int tj = 0; tj < 4; tj++)
            out[(i0 + ty + 16 * ti) * MROWS + j0 + tx + 16 * tj] =
                hsum2(acc[ti][tj]);
}

extern "C" void kernel_launch(void* const* d_in, const int* in_sizes, int n_in,
                              void* d_out, int out_size) {
    const float* x  = (const float*)d_in[0];
    const float* y  = (const float*)d_in[1];
    const float* W1 = (const float*)d_in[2];
    const float* W2 = (const float*)d_in[3];
    float* out = (float*)d_out;

    dim3 tgrid(DIM / 32, DIM / 32, 2);       // (16,16,2)
    transpose_w<<<tgrid, 256>>>(W1);

    dim3 ggrid(DIM / 64, NROWS / 64, 2);     // 256 blocks
    gemm_dual<<<ggrid, 256>>>(x, y);

    dim3 pgrid(MROWS / 64, NROWS / 64);      // 256 blocks
    pairwise_kernel<<<pgrid, 256>>>(W2, out);
}